// round 1
// baseline (speedup 1.0000x reference)
#include <cuda_runtime.h>
#include <math.h>
#include <stdint.h>

#define QL 512
#define ML 512
#define KL 1024
#define BS 8
#define NH 16
#define DH 64
#define DM 1024
#define DI 4096
#define NV 32000
#define NLAY 6
#define NQ (QL*BS)      // 4096 query rows
#define NK (KL*BS)      // 8192 key rows
#define ASCALE 0.125f   // 1/sqrt(64)

// ---------------- persistent scratch (static __device__, no allocs) ----------
static __device__ float g_core[NQ*DM];
static __device__ float g_xk[NK*DM];
static __device__ float g_q[NQ*DM];
static __device__ float g_kv[(size_t)NK*2*DM];
static __device__ float g_posbuf[KL*DM];
static __device__ float g_rk[KL*DM];
static __device__ float g_P[(size_t)BS*NH*QL*KL];   // AC scores, then probs (in place)
static __device__ float g_BD[(size_t)BS*NH*QL*KL];  // BD_raw scores
static __device__ float g_att[NQ*DM];
static __device__ float g_tmp[NQ*DM];
static __device__ float g_ff[(size_t)NQ*DI];
static __device__ float g_logits[(size_t)NQ*NV];

// ---------------- embedding lookup ------------------------------------------
__global__ void embed_kernel(const int* __restrict__ data, const float* __restrict__ embW) {
    int t = blockIdx.x;                 // 0..4095  (t = q*8+b)
    int tok = data[t];
    int c = threadIdx.x * 4;            // 256 threads * 4 = 1024
    float4 v = *(const float4*)(embW + (size_t)tok * DM + c);
    *(float4*)(g_core + (size_t)t * DM + c) = v;
}

// ---------------- sinusoidal relative positions ------------------------------
__global__ void pos_kernel() {
    int p = blockIdx.x;                 // 0..1023
    float ps = (float)(KL - 1 - p);
    for (int j = threadIdx.x; j < 512; j += 256) {
        float f = powf(10000.0f, -(float)j / 512.0f);
        float a = ps * f;
        g_posbuf[p * DM + j]       = sinf(a);
        g_posbuf[p * DM + 512 + j] = cosf(a);
    }
}

// ---------------- concat [mem_i ; core] -> g_xk ------------------------------
__global__ void concat_kernel(const float* __restrict__ mem_i) {
    int i = blockIdx.x * 256 + threadIdx.x;           // float4 index, 2,097,152 total
    const int HALF = ML * BS * DM / 4;                // 1,048,576
    float4 v = (i < HALF) ? ((const float4*)mem_i)[i]
                          : ((const float4*)g_core)[i - HALF];
    ((float4*)g_xk)[i] = v;
}

// ---------------- snapshot core -> new_mems slot -----------------------------
__global__ void copyout_kernel(float* __restrict__ dst) {
    int i = blockIdx.x * 256 + threadIdx.x;           // 1,048,576 float4
    ((float4*)dst)[i] = ((const float4*)g_core)[i];
}

// ---------------- classic SGEMM, C = A@B (+bias)(+relu), row-major -----------
// M%128==0, N%128==0, K%8==0 assumed (true for every call here).
template<int EPI>   // 0: none, 1: +bias, 2: +bias then relu
__global__ void sgemm_nn(const float* __restrict__ A, const float* __restrict__ Bm,
                         float* __restrict__ C, const float* __restrict__ bias,
                         int M, int N, int K) {
    __shared__ float As[8][128];
    __shared__ float Bs[8][128];
    int tid = threadIdx.x;
    int bx = blockIdx.x, by = blockIdx.y;
    const float* Ap = A + (size_t)(by * 128 + (tid >> 1)) * K + (tid & 1) * 4;
    const float* Bp = Bm + (size_t)(tid >> 5) * N + bx * 128 + (tid & 31) * 4;
    int tx = tid & 15, ty = tid >> 4;
    float acc[8][8] = {};
    for (int k0 = 0; k0 < K; k0 += 8) {
        float4 a = *(const float4*)(Ap + k0);
        float4 b = *(const float4*)(Bp + (size_t)k0 * N);
        int ar = tid >> 1, ak = (tid & 1) * 4;
        As[ak+0][ar] = a.x; As[ak+1][ar] = a.y; As[ak+2][ar] = a.z; As[ak+3][ar] = a.w;
        *(float4*)&Bs[tid >> 5][(tid & 31) * 4] = b;
        __syncthreads();
        #pragma unroll
        for (int kk = 0; kk < 8; kk++) {
            float4 a0 = *(float4*)&As[kk][ty * 8];
            float4 a1 = *(float4*)&As[kk][ty * 8 + 4];
            float4 b0 = *(float4*)&Bs[kk][tx * 8];
            float4 b1 = *(float4*)&Bs[kk][tx * 8 + 4];
            float av[8] = {a0.x,a0.y,a0.z,a0.w,a1.x,a1.y,a1.z,a1.w};
            float bw[8] = {b0.x,b0.y,b0.z,b0.w,b1.x,b1.y,b1.z,b1.w};
            #pragma unroll
            for (int e = 0; e < 8; e++)
                #pragma unroll
                for (int f = 0; f < 8; f++)
                    acc[e][f] += av[e] * bw[f];
        }
        __syncthreads();
    }
    #pragma unroll
    for (int e = 0; e < 8; e++) {
        size_t row = (size_t)(by * 128 + ty * 8 + e);
        float* cp = C + row * N + bx * 128 + tx * 8;
        #pragma unroll
        for (int f4 = 0; f4 < 2; f4++) {
            float4 o;
            o.x = acc[e][f4*4+0]; o.y = acc[e][f4*4+1];
            o.z = acc[e][f4*4+2]; o.w = acc[e][f4*4+3];
            if (EPI >= 1) {
                int col = bx * 128 + tx * 8 + f4 * 4;
                o.x += bias[col+0]; o.y += bias[col+1];
                o.z += bias[col+2]; o.w += bias[col+3];
            }
            if (EPI == 2) {
                o.x = fmaxf(o.x, 0.f); o.y = fmaxf(o.y, 0.f);
                o.z = fmaxf(o.z, 0.f); o.w = fmaxf(o.w, 0.f);
            }
            *(float4*)(cp + f4 * 4) = o;
        }
    }
}

// ---------------- SGEMM, C = A @ B^T (B stored [N,K] row-major) --------------
__global__ void sgemm_nt(const float* __restrict__ A, const float* __restrict__ Bt,
                         float* __restrict__ C, int M, int N, int K) {
    __shared__ float As[8][128];
    __shared__ float Bs[8][128];
    int tid = threadIdx.x;
    int bx = blockIdx.x, by = blockIdx.y;
    const float* Ap = A  + (size_t)(by * 128 + (tid >> 1)) * K + (tid & 1) * 4;
    const float* Bp = Bt + (size_t)(bx * 128 + (tid >> 1)) * K + (tid & 1) * 4;
    int tx = tid & 15, ty = tid >> 4;
    float acc[8][8] = {};
    for (int k0 = 0; k0 < K; k0 += 8) {
        float4 a = *(const float4*)(Ap + k0);
        float4 b = *(const float4*)(Bp + k0);
        int r = tid >> 1, kk4 = (tid & 1) * 4;
        As[kk4+0][r] = a.x; As[kk4+1][r] = a.y; As[kk4+2][r] = a.z; As[kk4+3][r] = a.w;
        Bs[kk4+0][r] = b.x; Bs[kk4+1][r] = b.y; Bs[kk4+2][r] = b.z; Bs[kk4+3][r] = b.w;
        __syncthreads();
        #pragma unroll
        for (int kk = 0; kk < 8; kk++) {
            float4 a0 = *(float4*)&As[kk][ty * 8];
            float4 a1 = *(float4*)&As[kk][ty * 8 + 4];
            float4 b0 = *(float4*)&Bs[kk][tx * 8];
            float4 b1 = *(float4*)&Bs[kk][tx * 8 + 4];
            float av[8] = {a0.x,a0.y,a0.z,a0.w,a1.x,a1.y,a1.z,a1.w};
            float bw[8] = {b0.x,b0.y,b0.z,b0.w,b1.x,b1.y,b1.z,b1.w};
            #pragma unroll
            for (int e = 0; e < 8; e++)
                #pragma unroll
                for (int f = 0; f < 8; f++)
                    acc[e][f] += av[e] * bw[f];
        }
        __syncthreads();
    }
    #pragma unroll
    for (int e = 0; e < 8; e++) {
        size_t row = (size_t)(by * 128 + ty * 8 + e);
        float* cp = C + row * N + bx * 128 + tx * 8;
        *(float4*)(cp)     = *(float4*)&acc[e][0];
        *(float4*)(cp + 4) = *(float4*)&acc[e][4];
    }
}

// ---------------- AC scores: (q + r_w_bias) . k ------------------------------
// grid (KL/64, QL/64, 128) ; bn = b*16+n ; out g_P[bn][i][j]
__global__ void ac_kernel(const float* __restrict__ rwb) {
    int jt = blockIdx.x, it = blockIdx.y, bn = blockIdx.z;
    int b = bn >> 4, n = bn & 15;
    __shared__ float Qs[64][68];   // [d][i]
    __shared__ float Ks[64][68];   // [d][j]
    int tid = threadIdx.x;
    int i0 = it * 64, j0 = jt * 64;
    for (int l = tid; l < 1024; l += 256) {
        int r = l >> 4, c = (l & 15) * 4;
        float4 qv = *(const float4*)&g_q[((size_t)(i0 + r) * BS + b) * DM + n * DH + c];
        float4 bv = *(const float4*)&rwb[n * DH + c];
        Qs[c+0][r] = qv.x + bv.x; Qs[c+1][r] = qv.y + bv.y;
        Qs[c+2][r] = qv.z + bv.z; Qs[c+3][r] = qv.w + bv.w;
        float4 kv = *(const float4*)&g_kv[((size_t)(j0 + r) * BS + b) * (2*DM) + n * DH + c];
        Ks[c+0][r] = kv.x; Ks[c+1][r] = kv.y; Ks[c+2][r] = kv.z; Ks[c+3][r] = kv.w;
    }
    __syncthreads();
    int tx = tid & 15, ty = tid >> 4;
    float acc[4][4] = {};
    #pragma unroll 8
    for (int d = 0; d < 64; d++) {
        float4 a = *(float4*)&Qs[d][ty * 4];
        float4 k = *(float4*)&Ks[d][tx * 4];
        float av[4] = {a.x,a.y,a.z,a.w}, kv2[4] = {k.x,k.y,k.z,k.w};
        #pragma unroll
        for (int e = 0; e < 4; e++)
            #pragma unroll
            for (int f = 0; f < 4; f++)
                acc[e][f] += av[e] * kv2[f];
    }
    #pragma unroll
    for (int e = 0; e < 4; e++) {
        int i = i0 + ty * 4 + e;
        float4 o = {acc[e][0], acc[e][1], acc[e][2], acc[e][3]};
        *(float4*)&g_P[((size_t)bn * QL + i) * KL + j0 + tx * 4] = o;
    }
}

// ---------------- BD_raw scores: (q + r_r_bias) . r_k ------------------------
__global__ void bd_kernel(const float* __restrict__ rrb) {
    int jt = blockIdx.x, it = blockIdx.y, bn = blockIdx.z;
    int b = bn >> 4, n = bn & 15;
    __shared__ float Qs[64][68];
    __shared__ float Rs[64][68];
    int tid = threadIdx.x;
    int i0 = it * 64, j0 = jt * 64;
    for (int l = tid; l < 1024; l += 256) {
        int r = l >> 4, c = (l & 15) * 4;
        float4 qv = *(const float4*)&g_q[((size_t)(i0 + r) * BS + b) * DM + n * DH + c];
        float4 bv = *(const float4*)&rrb[n * DH + c];
        Qs[c+0][r] = qv.x + bv.x; Qs[c+1][r] = qv.y + bv.y;
        Qs[c+2][r] = qv.z + bv.z; Qs[c+3][r] = qv.w + bv.w;
        float4 rv = *(const float4*)&g_rk[(size_t)(j0 + r) * DM + n * DH + c];
        Rs[c+0][r] = rv.x; Rs[c+1][r] = rv.y; Rs[c+2][r] = rv.z; Rs[c+3][r] = rv.w;
    }
    __syncthreads();
    int tx = tid & 15, ty = tid >> 4;
    float acc[4][4] = {};
    #pragma unroll 8
    for (int d = 0; d < 64; d++) {
        float4 a = *(float4*)&Qs[d][ty * 4];
        float4 k = *(float4*)&Rs[d][tx * 4];
        float av[4] = {a.x,a.y,a.z,a.w}, kv2[4] = {k.x,k.y,k.z,k.w};
        #pragma unroll
        for (int e = 0; e < 4; e++)
            #pragma unroll
            for (int f = 0; f < 4; f++)
                acc[e][f] += av[e] * kv2[f];
    }
    #pragma unroll
    for (int e = 0; e < 4; e++) {
        int i = i0 + ty * 4 + e;
        float4 o = {acc[e][0], acc[e][1], acc[e][2], acc[e][3]};
        *(float4*)&g_BD[((size_t)bn * QL + i) * KL + j0 + tx * 4] = o;
    }
}

// ---------------- combine + rel-shift + mask + softmax (in place into g_P) ---
__global__ void softmax_kernel() {
    int i = blockIdx.x, bn = blockIdx.y;
    const float* ac = &g_P[((size_t)bn * QL + i) * KL];
    const float* bd = &g_BD[((size_t)bn * QL + i) * KL];
    int tid = threadIdx.x;
    int lim = i + ML;                       // valid keys: j <= i + mlen
    float v[4]; float mx = -1e30f;
    #pragma unroll
    for (int r = 0; r < 4; r++) {
        int j = r * 256 + tid;
        float s = (j <= lim) ? ASCALE * (ac[j] + bd[j + QL - 1 - i]) : -1e30f;
        v[r] = s; mx = fmaxf(mx, s);
    }
    __shared__ float red[256];
    red[tid] = mx; __syncthreads();
    for (int st = 128; st > 0; st >>= 1) {
        if (tid < st) red[tid] = fmaxf(red[tid], red[tid + st]);
        __syncthreads();
    }
    mx = red[0]; __syncthreads();
    float sum = 0.f;
    #pragma unroll
    for (int r = 0; r < 4; r++) { v[r] = __expf(v[r] - mx); sum += v[r]; }
    red[tid] = sum; __syncthreads();
    for (int st = 128; st > 0; st >>= 1) {
        if (tid < st) red[tid] += red[tid + st];
        __syncthreads();
    }
    float inv = 1.0f / red[0];
    float* p = &g_P[((size_t)bn * QL + i) * KL];
    #pragma unroll
    for (int r = 0; r < 4; r++) p[r * 256 + tid] = v[r] * inv;
}

// ---------------- P @ V -> g_att ---------------------------------------------
// grid (QL/64, 128)
__global__ void pv_kernel() {
    int it = blockIdx.x, bn = blockIdx.y;
    int b = bn >> 4, n = bn & 15;
    __shared__ float Ps[32][68];   // [j][i]
    __shared__ float Vs[32][68];   // [j][d]
    int tid = threadIdx.x;
    int i0 = it * 64;
    int tx = tid & 15, ty = tid >> 4;
    float acc[4][4] = {};
    for (int jc = 0; jc < KL; jc += 32) {
        for (int l = tid; l < 512; l += 256) {
            int r = l >> 3, c = (l & 7) * 4;     // P tile: 64 i rows x 32 j
            float4 pv = *(const float4*)&g_P[((size_t)bn * QL + i0 + r) * KL + jc + c];
            Ps[c+0][r] = pv.x; Ps[c+1][r] = pv.y; Ps[c+2][r] = pv.z; Ps[c+3][r] = pv.w;
            int vr = l >> 4, vc = (l & 15) * 4;  // V tile: 32 j rows x 64 d
            float4 vv = *(const float4*)&g_kv[((size_t)(jc + vr) * BS + b) * (2*DM) + DM + n * DH + vc];
            *(float4*)&Vs[vr][vc] = vv;
        }
        __syncthreads();
        #pragma unroll
        for (int k = 0; k < 32; k++) {
            float4 a = *(float4*)&Ps[k][ty * 4];
            float4 w = *(float4*)&Vs[k][tx * 4];
            float av[4] = {a.x,a.y,a.z,a.w}, wv[4] = {w.x,w.y,w.z,w.w};
            #pragma unroll
            for (int e = 0; e < 4; e++)
                #pragma unroll
                for (int f = 0; f < 4; f++)
                    acc[e][f] += av[e] * wv[f];
        }
        __syncthreads();
    }
    #pragma unroll
    for (int e = 0; e < 4; e++) {
        int i = i0 + ty * 4 + e;
        float4 o = {acc[e][0], acc[e][1], acc[e][2], acc[e][3]};
        *(float4*)&g_att[((size_t)i * BS + b) * DM + n * DH + tx * 4] = o;
    }
}

// ---------------- residual add + LayerNorm (in place on g_core) --------------
__global__ void add_ln_kernel(float* __restrict__ io, const float* __restrict__ add,
                              const float* __restrict__ g, const float* __restrict__ bt) {
    int t = blockIdx.x, tid = threadIdx.x;
    size_t base = (size_t)t * DM;
    float x[4]; float s = 0.f, sq = 0.f;
    #pragma unroll
    for (int r = 0; r < 4; r++) {
        int d = r * 256 + tid;
        float v = io[base + d] + add[base + d];
        x[r] = v; s += v; sq += v * v;
    }
    __shared__ float rs[256], rq[256];
    rs[tid] = s; rq[tid] = sq; __syncthreads();
    for (int st = 128; st > 0; st >>= 1) {
        if (tid < st) { rs[tid] += rs[tid + st]; rq[tid] += rq[tid + st]; }
        __syncthreads();
    }
    float mean = rs[0] * (1.0f / DM);
    float var  = rq[0] * (1.0f / DM) - mean * mean;
    float rstd = rsqrtf(var + 1e-5f);
    #pragma unroll
    for (int r = 0; r < 4; r++) {
        int d = r * 256 + tid;
        io[base + d] = (x[r] - mean) * rstd * g[d] + bt[d];
    }
}

// ---------------- per-token loss from logits ---------------------------------
__global__ void loss_kernel(const int* __restrict__ target, float* __restrict__ out) {
    int t = blockIdx.x, tid = threadIdx.x;
    const float* row = &g_logits[(size_t)t * NV];
    float mx = -1e30f;
    for (int j = tid; j < NV; j += 256) mx = fmaxf(mx, row[j]);
    __shared__ float red[256];
    red[tid] = mx; __syncthreads();
    for (int st = 128; st > 0; st >>= 1) {
        if (tid < st) red[tid] = fmaxf(red[tid], red[tid + st]);
        __syncthreads();
    }
    mx = red[0]; __syncthreads();
    float s = 0.f;
    for (int j = tid; j < NV; j += 256) s += __expf(row[j] - mx);
    red[tid] = s; __syncthreads();
    for (int st = 128; st > 0; st >>= 1) {
        if (tid < st) red[tid] += red[tid + st];
        __syncthreads();
    }
    if (tid == 0) {
        float lse = logf(red[0]) + mx;
        out[t] = lse - row[target[t]];
    }
}

// ---------------- host orchestration -----------------------------------------
extern "C" void kernel_launch(void* const* d_in, const int* in_sizes, int n_in,
                              void* d_out, int out_size) {
    const int*   data   = (const int*)d_in[0];
    const int*   target = (const int*)d_in[1];
    const float* memory = (const float*)d_in[2];
    const float* embW   = (const float*)d_in[3];
    const float* rwb    = (const float*)d_in[4];
    const float* rrb    = (const float*)d_in[5];
    const float* Wq     = (const float*)d_in[6];
    const float* Wkv    = (const float*)d_in[7];
    const float* Wr     = (const float*)d_in[8];
    const float* Wo     = (const float*)d_in[9];
    const float* W1     = (const float*)d_in[10];
    const float* b1     = (const float*)d_in[11];
    const float* W2     = (const float*)d_in[12];
    const float* b2     = (const float*)d_in[13];
    const float* ln1g   = (const float*)d_in[14];
    const float* ln1b   = (const float*)d_in[15];
    const float* ln2g   = (const float*)d_in[16];
    const float* ln2b   = (const float*)d_in[17];

    float* out = (float*)d_out;
    const long SLAB = (long)ML * BS * DM;                // 4,194,304
    float* out_mems = (out_size >= 4096L + NLAY * SLAB) ? out + 4096 : nullptr;

    // device pointers to static scratch for the generic GEMMs
    float *p_core, *p_xk, *p_q, *p_kv, *p_pos, *p_rk, *p_att, *p_tmp, *p_ff, *p_logits;
    cudaGetSymbolAddress((void**)&p_core,   g_core);
    cudaGetSymbolAddress((void**)&p_xk,     g_xk);
    cudaGetSymbolAddress((void**)&p_q,      g_q);
    cudaGetSymbolAddress((void**)&p_kv,     g_kv);
    cudaGetSymbolAddress((void**)&p_pos,    g_posbuf);
    cudaGetSymbolAddress((void**)&p_rk,     g_rk);
    cudaGetSymbolAddress((void**)&p_att,    g_att);
    cudaGetSymbolAddress((void**)&p_tmp,    g_tmp);
    cudaGetSymbolAddress((void**)&p_ff,     g_ff);
    cudaGetSymbolAddress((void**)&p_logits, g_logits);

    embed_kernel<<<NQ, 256>>>(data, embW);
    pos_kernel<<<KL, 256>>>();

    for (int L = 0; L < NLAY; L++) {
        if (out_mems)
            copyout_kernel<<<4096, 256>>>(out_mems + (long)L * SLAB);   // hids[L]
        concat_kernel<<<8192, 256>>>(memory + (long)L * SLAB);

        sgemm_nn<0><<<dim3( 8, 32), 256>>>(p_core, Wq  + (long)L*DM*DM,   p_q,  nullptr, NQ, DM,   DM);
        sgemm_nn<0><<<dim3(16, 64), 256>>>(p_xk,   Wkv + (long)L*DM*2*DM, p_kv, nullptr, NK, 2*DM, DM);
        sgemm_nn<0><<<dim3( 8,  8), 256>>>(p_pos,  Wr  + (long)L*DM*DM,   p_rk, nullptr, KL, DM,   DM);

        ac_kernel<<<dim3(16, 8, 128), 256>>>(rwb);
        bd_kernel<<<dim3(16, 8, 128), 256>>>(rrb);
        softmax_kernel<<<dim3(QL, 128), 256>>>();
        pv_kernel<<<dim3(8, 128), 256>>>();

        sgemm_nn<0><<<dim3(8, 32), 256>>>(p_att, Wo + (long)L*DM*DM, p_tmp, nullptr, NQ, DM, DM);
        add_ln_kernel<<<NQ, 256>>>(p_core, p_tmp, ln1g + L*DM, ln1b + L*DM);

        sgemm_nn<2><<<dim3(32, 32), 256>>>(p_core, W1 + (long)L*DM*DI, p_ff,  b1 + L*DI, NQ, DI, DM);
        sgemm_nn<1><<<dim3( 8, 32), 256>>>(p_ff,   W2 + (long)L*DI*DM, p_tmp, b2 + L*DM, NQ, DM, DI);
        add_ln_kernel<<<NQ, 256>>>(p_core, p_tmp, ln2g + L*DM, ln2b + L*DM);
    }

    sgemm_nt<<<dim3(NV / 128, NQ / 128), 256>>>(p_core, embW, p_logits, NQ, NV, DM);
    loss_kernel<<<NQ, 256>>>(target, out);
}

// round 8
// speedup vs baseline: 1.7605x; 1.7605x over previous
#include <cuda_runtime.h>
#include <cuda_bf16.h>
#include <math.h>
#include <stdint.h>

#define QL 512
#define ML 512
#define KL 1024
#define BS 8
#define NH 16
#define DH 64
#define DM 1024
#define DI 4096
#define NV 32000
#define NLAY 6
#define NQ (QL*BS)
#define NK (KL*BS)
#define ASCALE 0.125f

// ---------------- persistent scratch ----------------------------------------
static __device__ float g_core[NQ*DM];
static __device__ float g_xk[NK*DM];
static __device__ float g_q[NQ*DM];
static __device__ float g_kv[(size_t)NK*2*DM];
static __device__ float g_posbuf[KL*DM];
static __device__ float g_rk[KL*DM];
static __device__ float g_P[(size_t)BS*NH*QL*KL];
static __device__ float g_BD[(size_t)BS*NH*QL*KL];
static __device__ float g_att[NQ*DM];
static __device__ float g_tmp[NQ*DM];
static __device__ float g_ff[(size_t)NQ*DI];
static __device__ float g_logits[(size_t)NQ*NV];
// bf16 triple-K operand buffers
static __device__ __nv_bfloat16 g_a3[(size_t)NQ*3*DI];
static __device__ __nv_bfloat16 g_w3[(size_t)DI*3*DM];
static __device__ __nv_bfloat16 g_emb3[(size_t)NV*3*DM];
static __device__ __nv_bfloat16 g_pos3[(size_t)KL*3*DM];

__device__ __forceinline__ uint32_t smem_u32(const void* p) {
    uint32_t a;
    asm("{ .reg .u64 t; cvta.to.shared.u64 t, %1; cvt.u32.u64 %0, t; }" : "=r"(a) : "l"(p));
    return a;
}

// ==================== HMMA bf16x3 GEMM (mma.sync, direct LDS fragments) ======
// C[M,N] = A3[M,K3] . B3[N,K3]^T, fp32 accumulate.
// A3 rows are [h|l|h]; B3 rows are [h|h|l]  =>  hh + lh + hl  (drops ll ~2^-16)
// M,N multiples of 128; K3 multiple of 32.
#define AST 40                      // smem row stride in bf16 (80B; conflict-free)
#define TILE_ELEMS (128*AST)

template<int EPI>   // 0 none, 1 +bias, 2 +bias+relu
__global__ __launch_bounds__(256)
void tc_gemm(const __nv_bfloat16* __restrict__ A3, const __nv_bfloat16* __restrict__ B3,
             float* __restrict__ C, const float* __restrict__ bias,
             int M, int N, int K3) {
    __shared__ __align__(16) __nv_bfloat16 As[2][TILE_ELEMS];
    __shared__ __align__(16) __nv_bfloat16 Bs[2][TILE_ELEMS];
    int tid = threadIdx.x, wid = tid >> 5, lane = tid & 31;
    int warp_m = wid >> 2, warp_n = wid & 3;        // 2 x 4 warp grid
    int gid = lane >> 2, tig = lane & 3;            // mma fragment coords
    int n0 = blockIdx.x * 128, m0 = blockIdx.y * 128;
    const __nv_bfloat16* Ag = A3 + (size_t)m0 * K3;
    const __nv_bfloat16* Bg = B3 + (size_t)n0 * K3;
    int NC = K3 >> 5;
    uint32_t sA = smem_u32(As), sB = smem_u32(Bs);
    int lrow = tid >> 2, lseg = tid & 3;            // 16B segment loader coords

    // prefetch tile 0
    #pragma unroll
    for (int i = 0; i < 2; i++) {
        int row = lrow + i * 64;
        uint32_t da = sA + (uint32_t)(row * AST + lseg * 8) * 2;
        uint32_t db = sB + (uint32_t)(row * AST + lseg * 8) * 2;
        const void* ga = Ag + (size_t)row * K3 + lseg * 8;
        const void* gb = Bg + (size_t)row * K3 + lseg * 8;
        asm volatile("cp.async.cg.shared.global [%0], [%1], 16;\n" :: "r"(da), "l"(ga));
        asm volatile("cp.async.cg.shared.global [%0], [%1], 16;\n" :: "r"(db), "l"(gb));
    }
    asm volatile("cp.async.commit_group;\n");

    float acc[4][4][4] = {};

    for (int c = 0; c < NC; c++) {
        int cur = c & 1;
        if (c + 1 < NC) {
            int nx = cur ^ 1, k0 = (c + 1) * 32;
            #pragma unroll
            for (int i = 0; i < 2; i++) {
                int row = lrow + i * 64;
                uint32_t da = sA + (uint32_t)(nx * TILE_ELEMS + row * AST + lseg * 8) * 2;
                uint32_t db = sB + (uint32_t)(nx * TILE_ELEMS + row * AST + lseg * 8) * 2;
                const void* ga = Ag + (size_t)row * K3 + k0 + lseg * 8;
                const void* gb = Bg + (size_t)row * K3 + k0 + lseg * 8;
                asm volatile("cp.async.cg.shared.global [%0], [%1], 16;\n" :: "r"(da), "l"(ga));
                asm volatile("cp.async.cg.shared.global [%0], [%1], 16;\n" :: "r"(db), "l"(gb));
            }
            asm volatile("cp.async.commit_group;\n");
            asm volatile("cp.async.wait_group 1;\n");
        } else {
            asm volatile("cp.async.wait_group 0;\n");
        }
        __syncthreads();

        const __nv_bfloat16* Ab = &As[cur][0];
        const __nv_bfloat16* Bb = &Bs[cur][0];
        #pragma unroll
        for (int ks = 0; ks < 2; ks++) {
            int kk = ks * 16;
            uint32_t a_frag[4][4];
            uint32_t b_frag[4][2];
            // A fragments per documented m16n8k16 layout:
            //   a0=(gid, tig*2) a1=(gid+8, tig*2) a2=(gid, tig*2+8) a3=(gid+8, tig*2+8)
            #pragma unroll
            for (int mt = 0; mt < 4; mt++) {
                int r0 = (warp_m * 64 + mt * 16 + gid) * AST + kk + tig * 2;
                a_frag[mt][0] = *(const uint32_t*)(Ab + r0);
                a_frag[mt][1] = *(const uint32_t*)(Ab + r0 + 8 * AST);
                a_frag[mt][2] = *(const uint32_t*)(Ab + r0 + 8);
                a_frag[mt][3] = *(const uint32_t*)(Ab + r0 + 8 * AST + 8);
            }
            // B fragments: b0=(k=tig*2, n=gid) b1=(k=tig*2+8, n=gid); smem is [n][k]
            #pragma unroll
            for (int nt = 0; nt < 4; nt++) {
                int rn = (warp_n * 32 + nt * 8 + gid) * AST + kk + tig * 2;
                b_frag[nt][0] = *(const uint32_t*)(Bb + rn);
                b_frag[nt][1] = *(const uint32_t*)(Bb + rn + 8);
            }
            #pragma unroll
            for (int mt = 0; mt < 4; mt++)
                #pragma unroll
                for (int nt = 0; nt < 4; nt++) {
                    asm volatile(
                        "mma.sync.aligned.m16n8k16.row.col.f32.bf16.bf16.f32 "
                        "{%0,%1,%2,%3}, {%4,%5,%6,%7}, {%8,%9}, {%0,%1,%2,%3};\n"
                        : "+f"(acc[mt][nt][0]), "+f"(acc[mt][nt][1]),
                          "+f"(acc[mt][nt][2]), "+f"(acc[mt][nt][3])
                        : "r"(a_frag[mt][0]), "r"(a_frag[mt][1]),
                          "r"(a_frag[mt][2]), "r"(a_frag[mt][3]),
                          "r"(b_frag[nt][0]), "r"(b_frag[nt][1]));
                }
        }
        __syncthreads();
    }

    // epilogue: c0,c1=(gid, tig*2..+1); c2,c3=(gid+8, ...)
    #pragma unroll
    for (int mt = 0; mt < 4; mt++) {
        #pragma unroll
        for (int nt = 0; nt < 4; nt++) {
            int row0 = m0 + warp_m * 64 + mt * 16 + gid;
            int col  = n0 + warp_n * 32 + nt * 8 + tig * 2;
            float2 v0, v1;
            v0.x = acc[mt][nt][0]; v0.y = acc[mt][nt][1];
            v1.x = acc[mt][nt][2]; v1.y = acc[mt][nt][3];
            if (EPI >= 1) {
                float bx = bias[col], by = bias[col + 1];
                v0.x += bx; v0.y += by; v1.x += bx; v1.y += by;
            }
            if (EPI == 2) {
                v0.x = fmaxf(v0.x, 0.f); v0.y = fmaxf(v0.y, 0.f);
                v1.x = fmaxf(v1.x, 0.f); v1.y = fmaxf(v1.y, 0.f);
            }
            *(float2*)(C + (size_t)row0 * N + col)       = v0;
            *(float2*)(C + (size_t)(row0 + 8) * N + col) = v1;
        }
    }
}

// ==================== fp32 -> bf16 triple-K conversions ======================
// MODE 0 (A operand): Y row = [h | l | h]
// MODE 1 (B operand): Y row = [h | h | l]
template<int MODE>
__global__ void split_rows_kernel(const float* __restrict__ X, __nv_bfloat16* __restrict__ Y,
                                  int kshift, long total) {
    long e = ((long)blockIdx.x * 256 + threadIdx.x) * 4;
    if (e >= total) return;
    int K = 1 << kshift;
    long r = e >> kshift; int c = (int)(e & (K - 1));
    float4 v = *(const float4*)(X + e);
    __nv_bfloat16 hx = __float2bfloat16(v.x), hy = __float2bfloat16(v.y);
    __nv_bfloat16 hz = __float2bfloat16(v.z), hw = __float2bfloat16(v.w);
    __nv_bfloat16 lx = __float2bfloat16(v.x - __bfloat162float(hx));
    __nv_bfloat16 ly = __float2bfloat16(v.y - __bfloat162float(hy));
    __nv_bfloat16 lz = __float2bfloat16(v.z - __bfloat162float(hz));
    __nv_bfloat16 lw = __float2bfloat16(v.w - __bfloat162float(hw));
    __nv_bfloat16* yb = Y + r * 3 * K;
    __nv_bfloat162 h01; h01.x = hx; h01.y = hy;
    __nv_bfloat162 h23; h23.x = hz; h23.y = hw;
    __nv_bfloat162 l01; l01.x = lx; l01.y = ly;
    __nv_bfloat162 l23; l23.x = lz; l23.y = lw;
    *(__nv_bfloat162*)(yb + c)     = h01; *(__nv_bfloat162*)(yb + c + 2)     = h23;
    if (MODE == 0) {   // [h | l | h]
        *(__nv_bfloat162*)(yb + K + c)   = l01; *(__nv_bfloat162*)(yb + K + c + 2)   = l23;
        *(__nv_bfloat162*)(yb + 2*K + c) = h01; *(__nv_bfloat162*)(yb + 2*K + c + 2) = h23;
    } else {           // [h | h | l]
        *(__nv_bfloat162*)(yb + K + c)   = h01; *(__nv_bfloat162*)(yb + K + c + 2)   = h23;
        *(__nv_bfloat162*)(yb + 2*K + c) = l01; *(__nv_bfloat162*)(yb + 2*K + c + 2) = l23;
    }
}

// W[K,N] -> Y[N,3K] = [h | h | l]  (B operand: transpose + split)
__global__ void split_tr_kernel(const float* __restrict__ W, __nv_bfloat16* __restrict__ Y,
                                int K, int N) {
    __shared__ float s[32][33];
    int n0 = blockIdx.x * 32, k0 = blockIdx.y * 32;
    int tx = threadIdx.x, ty = threadIdx.y;
    for (int i = ty; i < 32; i += 8)
        s[i][tx] = W[(size_t)(k0 + i) * N + n0 + tx];
    __syncthreads();
    for (int i = ty; i < 32; i += 8) {
        int n = n0 + i, k = k0 + tx;
        float v = s[tx][i];
        __nv_bfloat16 h = __float2bfloat16(v);
        __nv_bfloat16 l = __float2bfloat16(v - __bfloat162float(h));
        __nv_bfloat16* yb = Y + (size_t)n * 3 * K;
        yb[k] = h; yb[K + k] = h; yb[2*K + k] = l;
    }
}

// ==================== misc kernels ===========================================
__global__ void embed_kernel(const int* __restrict__ data, const float* __restrict__ embW) {
    int t = blockIdx.x;
    int tok = data[t];
    int c = threadIdx.x * 4;
    float4 v = *(const float4*)(embW + (size_t)tok * DM + c);
    *(float4*)(g_core + (size_t)t * DM + c) = v;
}

__global__ void pos_kernel() {
    int p = blockIdx.x;
    float ps = (float)(KL - 1 - p);
    for (int j = threadIdx.x; j < 512; j += 256) {
        float f = powf(10000.0f, -(float)j / 512.0f);
        float a = ps * f;
        g_posbuf[p * DM + j]       = sinf(a);
        g_posbuf[p * DM + 512 + j] = cosf(a);
    }
}

__global__ void concat_kernel(const float* __restrict__ mem_i) {
    int i = blockIdx.x * 256 + threadIdx.x;
    const int HALF = ML * BS * DM / 4;
    float4 v = (i < HALF) ? ((const float4*)mem_i)[i]
                          : ((const float4*)g_core)[i - HALF];
    ((float4*)g_xk)[i] = v;
}

__global__ void copyout_kernel(float* __restrict__ dst) {
    int i = blockIdx.x * 256 + threadIdx.x;
    ((float4*)dst)[i] = ((const float4*)g_core)[i];
}

__global__ void ac_kernel(const float* __restrict__ rwb) {
    int jt = blockIdx.x, it = blockIdx.y, bn = blockIdx.z;
    int b = bn >> 4, n = bn & 15;
    __shared__ float Qs[64][68];
    __shared__ float Ks[64][68];
    int tid = threadIdx.x;
    int i0 = it * 64, j0 = jt * 64;
    for (int l = tid; l < 1024; l += 256) {
        int r = l >> 4, c = (l & 15) * 4;
        float4 qv = *(const float4*)&g_q[((size_t)(i0 + r) * BS + b) * DM + n * DH + c];
        float4 bv = *(const float4*)&rwb[n * DH + c];
        Qs[c+0][r] = qv.x + bv.x; Qs[c+1][r] = qv.y + bv.y;
        Qs[c+2][r] = qv.z + bv.z; Qs[c+3][r] = qv.w + bv.w;
        float4 kv = *(const float4*)&g_kv[((size_t)(j0 + r) * BS + b) * (2*DM) + n * DH + c];
        Ks[c+0][r] = kv.x; Ks[c+1][r] = kv.y; Ks[c+2][r] = kv.z; Ks[c+3][r] = kv.w;
    }
    __syncthreads();
    int tx = tid & 15, ty = tid >> 4;
    float acc[4][4] = {};
    #pragma unroll 8
    for (int d = 0; d < 64; d++) {
        float4 a = *(float4*)&Qs[d][ty * 4];
        float4 k = *(float4*)&Ks[d][tx * 4];
        float av[4] = {a.x,a.y,a.z,a.w}, kv2[4] = {k.x,k.y,k.z,k.w};
        #pragma unroll
        for (int e = 0; e < 4; e++)
            #pragma unroll
            for (int f = 0; f < 4; f++)
                acc[e][f] += av[e] * kv2[f];
    }
    #pragma unroll
    for (int e = 0; e < 4; e++) {
        int i = i0 + ty * 4 + e;
        float4 o = {acc[e][0], acc[e][1], acc[e][2], acc[e][3]};
        *(float4*)&g_P[((size_t)bn * QL + i) * KL + j0 + tx * 4] = o;
    }
}

__global__ void bd_kernel(const float* __restrict__ rrb) {
    int jt = blockIdx.x, it = blockIdx.y, bn = blockIdx.z;
    int b = bn >> 4, n = bn & 15;
    __shared__ float Qs[64][68];
    __shared__ float Rs[64][68];
    int tid = threadIdx.x;
    int i0 = it * 64, j0 = jt * 64;
    for (int l = tid; l < 1024; l += 256) {
        int r = l >> 4, c = (l & 15) * 4;
        float4 qv = *(const float4*)&g_q[((size_t)(i0 + r) * BS + b) * DM + n * DH + c];
        float4 bv = *(const float4*)&rrb[n * DH + c];
        Qs[c+0][r] = qv.x + bv.x; Qs[c+1][r] = qv.y + bv.y;
        Qs[c+2][r] = qv.z + bv.z; Qs[c+3][r] = qv.w + bv.w;
        float4 rv = *(const float4*)&g_rk[(size_t)(j0 + r) * DM + n * DH + c];
        Rs[c+0][r] = rv.x; Rs[c+1][r] = rv.y; Rs[c+2][r] = rv.z; Rs[c+3][r] = rv.w;
    }
    __syncthreads();
    int tx = tid & 15, ty = tid >> 4;
    float acc[4][4] = {};
    #pragma unroll 8
    for (int d = 0; d < 64; d++) {
        float4 a = *(float4*)&Qs[d][ty * 4];
        float4 k = *(float4*)&Rs[d][tx * 4];
        float av[4] = {a.x,a.y,a.z,a.w}, kv2[4] = {k.x,k.y,k.z,k.w};
        #pragma unroll
        for (int e = 0; e < 4; e++)
            #pragma unroll
            for (int f = 0; f < 4; f++)
                acc[e][f] += av[e] * kv2[f];
    }
    #pragma unroll
    for (int e = 0; e < 4; e++) {
        int i = i0 + ty * 4 + e;
        float4 o = {acc[e][0], acc[e][1], acc[e][2], acc[e][3]};
        *(float4*)&g_BD[((size_t)bn * QL + i) * KL + j0 + tx * 4] = o;
    }
}

__global__ void softmax_kernel() {
    int i = blockIdx.x, bn = blockIdx.y;
    const float* ac = &g_P[((size_t)bn * QL + i) * KL];
    const float* bd = &g_BD[((size_t)bn * QL + i) * KL];
    int tid = threadIdx.x;
    int lim = i + ML;
    float v[4]; float mx = -1e30f;
    #pragma unroll
    for (int r = 0; r < 4; r++) {
        int j = r * 256 + tid;
        float s = (j <= lim) ? ASCALE * (ac[j] + bd[j + QL - 1 - i]) : -1e30f;
        v[r] = s; mx = fmaxf(mx, s);
    }
    __shared__ float red[256];
    red[tid] = mx; __syncthreads();
    for (int st = 128; st > 0; st >>= 1) {
        if (tid < st) red[tid] = fmaxf(red[tid], red[tid + st]);
        __syncthreads();
    }
    mx = red[0]; __syncthreads();
    float sum = 0.f;
    #pragma unroll
    for (int r = 0; r < 4; r++) { v[r] = __expf(v[r] - mx); sum += v[r]; }
    red[tid] = sum; __syncthreads();
    for (int st = 128; st > 0; st >>= 1) {
        if (tid < st) red[tid] += red[tid + st];
        __syncthreads();
    }
    float inv = 1.0f / red[0];
    float* p = &g_P[((size_t)bn * QL + i) * KL];
    #pragma unroll
    for (int r = 0; r < 4; r++) p[r * 256 + tid] = v[r] * inv;
}

__global__ void pv_kernel() {
    int it = blockIdx.x, bn = blockIdx.y;
    int b = bn >> 4, n = bn & 15;
    __shared__ float Ps[32][68];
    __shared__ float Vs[32][68];
    int tid = threadIdx.x;
    int i0 = it * 64;
    int tx = tid & 15, ty = tid >> 4;
    float acc[4][4] = {};
    for (int jc = 0; jc < KL; jc += 32) {
        for (int l = tid; l < 512; l += 256) {
            int r = l >> 3, c = (l & 7) * 4;
            float4 pv = *(const float4*)&g_P[((size_t)bn * QL + i0 + r) * KL + jc + c];
            Ps[c+0][r] = pv.x; Ps[c+1][r] = pv.y; Ps[c+2][r] = pv.z; Ps[c+3][r] = pv.w;
            int vr = l >> 4, vc = (l & 15) * 4;
            float4 vv = *(const float4*)&g_kv[((size_t)(jc + vr) * BS + b) * (2*DM) + DM + n * DH + vc];
            *(float4*)&Vs[vr][vc] = vv;
        }
        __syncthreads();
        #pragma unroll
        for (int k = 0; k < 32; k++) {
            float4 a = *(float4*)&Ps[k][ty * 4];
            float4 w = *(float4*)&Vs[k][tx * 4];
            float av[4] = {a.x,a.y,a.z,a.w}, wv[4] = {w.x,w.y,w.z,w.w};
            #pragma unroll
            for (int e = 0; e < 4; e++)
                #pragma unroll
                for (int f = 0; f < 4; f++)
                    acc[e][f] += av[e] * wv[f];
        }
        __syncthreads();
    }
    #pragma unroll
    for (int e = 0; e < 4; e++) {
        int i = i0 + ty * 4 + e;
        float4 o = {acc[e][0], acc[e][1], acc[e][2], acc[e][3]};
        *(float4*)&g_att[((size_t)i * BS + b) * DM + n * DH + tx * 4] = o;
    }
}

__global__ void add_ln_kernel(float* __restrict__ io, const float* __restrict__ add,
                              const float* __restrict__ g, const float* __restrict__ bt) {
    int t = blockIdx.x, tid = threadIdx.x;
    size_t base = (size_t)t * DM;
    float x[4]; float s = 0.f, sq = 0.f;
    #pragma unroll
    for (int r = 0; r < 4; r++) {
        int d = r * 256 + tid;
        float v = io[base + d] + add[base + d];
        x[r] = v; s += v; sq += v * v;
    }
    __shared__ float rs[256], rq[256];
    rs[tid] = s; rq[tid] = sq; __syncthreads();
    for (int st = 128; st > 0; st >>= 1) {
        if (tid < st) { rs[tid] += rs[tid + st]; rq[tid] += rq[tid + st]; }
        __syncthreads();
    }
    float mean = rs[0] * (1.0f / DM);
    float var  = rq[0] * (1.0f / DM) - mean * mean;
    float rstd = rsqrtf(var + 1e-5f);
    #pragma unroll
    for (int r = 0; r < 4; r++) {
        int d = r * 256 + tid;
        io[base + d] = (x[r] - mean) * rstd * g[d] + bt[d];
    }
}

__global__ void loss_kernel(const int* __restrict__ target, float* __restrict__ out) {
    int t = blockIdx.x, tid = threadIdx.x;
    const float* row = &g_logits[(size_t)t * NV];
    float mx = -1e30f;
    for (int j = tid; j < NV; j += 256) mx = fmaxf(mx, row[j]);
    __shared__ float red[256];
    red[tid] = mx; __syncthreads();
    for (int st = 128; st > 0; st >>= 1) {
        if (tid < st) red[tid] = fmaxf(red[tid], red[tid + st]);
        __syncthreads();
    }
    mx = red[0]; __syncthreads();
    float s = 0.f;
    for (int j = tid; j < NV; j += 256) s += __expf(row[j] - mx);
    red[tid] = s; __syncthreads();
    for (int st = 128; st > 0; st >>= 1) {
        if (tid < st) red[tid] += red[tid + st];
        __syncthreads();
    }
    if (tid == 0) {
        float lse = logf(red[0]) + mx;
        out[t] = lse - row[target[t]];
    }
}

// ==================== host orchestration =====================================
static void gemm3(const __nv_bfloat16* A3, const __nv_bfloat16* B3, float* C,
                  const float* bias, int M, int N, int K3, int epi) {
    dim3 grid(N / 128, M / 128);
    if (epi == 0)      tc_gemm<0><<<grid, 256>>>(A3, B3, C, bias, M, N, K3);
    else if (epi == 1) tc_gemm<1><<<grid, 256>>>(A3, B3, C, bias, M, N, K3);
    else               tc_gemm<2><<<grid, 256>>>(A3, B3, C, bias, M, N, K3);
}
static void split_rowsA(const float* X, __nv_bfloat16* Y, long R, int kshift) {
    long total = R << kshift;
    long blocks = (total / 4 + 255) / 256;
    split_rows_kernel<0><<<(int)blocks, 256>>>(X, Y, kshift, total);
}
static void split_rowsB(const float* X, __nv_bfloat16* Y, long R, int kshift) {
    long total = R << kshift;
    long blocks = (total / 4 + 255) / 256;
    split_rows_kernel<1><<<(int)blocks, 256>>>(X, Y, kshift, total);
}
static void split_tr(const float* W, __nv_bfloat16* Y, int K, int N) {
    split_tr_kernel<<<dim3(N / 32, K / 32), dim3(32, 8)>>>(W, Y, K, N);
}

extern "C" void kernel_launch(void* const* d_in, const int* in_sizes, int n_in,
                              void* d_out, int out_size) {
    const int*   data   = (const int*)d_in[0];
    const int*   target = (const int*)d_in[1];
    const float* memory = (const float*)d_in[2];
    const float* embW   = (const float*)d_in[3];
    const float* rwb    = (const float*)d_in[4];
    const float* rrb    = (const float*)d_in[5];
    const float* Wq     = (const float*)d_in[6];
    const float* Wkv    = (const float*)d_in[7];
    const float* Wr     = (const float*)d_in[8];
    const float* Wo     = (const float*)d_in[9];
    const float* W1     = (const float*)d_in[10];
    const float* b1     = (const float*)d_in[11];
    const float* W2     = (const float*)d_in[12];
    const float* b2     = (const float*)d_in[13];
    const float* ln1g   = (const float*)d_in[14];
    const float* ln1b   = (const float*)d_in[15];
    const float* ln2g   = (const float*)d_in[16];
    const float* ln2b   = (const float*)d_in[17];

    float* out = (float*)d_out;
    const long SLAB = (long)ML * BS * DM;
    float* out_mems = (out_size >= 4096L + NLAY * SLAB) ? out + 4096 : nullptr;

    float *p_core, *p_q, *p_kv, *p_pos, *p_rk, *p_att, *p_tmp, *p_ff, *p_xk, *p_logits;
    __nv_bfloat16 *p_a3, *p_w3, *p_emb3, *p_pos3;
    cudaGetSymbolAddress((void**)&p_core,   g_core);
    cudaGetSymbolAddress((void**)&p_xk,     g_xk);
    cudaGetSymbolAddress((void**)&p_q,      g_q);
    cudaGetSymbolAddress((void**)&p_kv,     g_kv);
    cudaGetSymbolAddress((void**)&p_pos,    g_posbuf);
    cudaGetSymbolAddress((void**)&p_rk,     g_rk);
    cudaGetSymbolAddress((void**)&p_att,    g_att);
    cudaGetSymbolAddress((void**)&p_tmp,    g_tmp);
    cudaGetSymbolAddress((void**)&p_ff,     g_ff);
    cudaGetSymbolAddress((void**)&p_logits, g_logits);
    cudaGetSymbolAddress((void**)&p_a3,     g_a3);
    cudaGetSymbolAddress((void**)&p_w3,     g_w3);
    cudaGetSymbolAddress((void**)&p_emb3,   g_emb3);
    cudaGetSymbolAddress((void**)&p_pos3,   g_pos3);

    embed_kernel<<<NQ, 256>>>(data, embW);
    pos_kernel<<<KL, 256>>>();
    split_rowsA(p_pos, p_pos3, KL, 10);         // pos is an A operand -> [h|l|h]
    split_rowsB(embW, p_emb3, NV, 10);          // emb is the logits B operand -> [h|h|l]

    for (int L = 0; L < NLAY; L++) {
        if (out_mems)
            copyout_kernel<<<4096, 256>>>(out_mems + (long)L * SLAB);
        concat_kernel<<<8192, 256>>>(memory + (long)L * SLAB);

        // q = core @ Wq
        split_rowsA(p_core, p_a3, NQ, 10);
        split_tr(Wq + (long)L*DM*DM, p_w3, DM, DM);
        gemm3(p_a3, p_w3, p_q, nullptr, NQ, DM, 3*DM, 0);
        // kv = xk @ Wkv
        split_rowsA(p_xk, p_a3, NK, 10);
        split_tr(Wkv + (long)L*DM*2*DM, p_w3, DM, 2*DM);
        gemm3(p_a3, p_w3, p_kv, nullptr, NK, 2*DM, 3*DM, 0);
        // rk = pos @ Wr
        split_tr(Wr + (long)L*DM*DM, p_w3, DM, DM);
        gemm3(p_pos3, p_w3, p_rk, nullptr, KL, DM, 3*DM, 0);

        ac_kernel<<<dim3(16, 8, 128), 256>>>(rwb);
        bd_kernel<<<dim3(16, 8, 128), 256>>>(rrb);
        softmax_kernel<<<dim3(QL, 128), 256>>>();
        pv_kernel<<<dim3(8, 128), 256>>>();

        // attn_out = att @ Wo
        split_rowsA(p_att, p_a3, NQ, 10);
        split_tr(Wo + (long)L*DM*DM, p_w3, DM, DM);
        gemm3(p_a3, p_w3, p_tmp, nullptr, NQ, DM, 3*DM, 0);
        add_ln_kernel<<<NQ, 256>>>(p_core, p_tmp, ln1g + L*DM, ln1b + L*DM);

        // ff = relu(core@W1+b1) @ W2 + b2
        split_rowsA(p_core, p_a3, NQ, 10);
        split_tr(W1 + (long)L*DM*DI, p_w3, DM, DI);
        gemm3(p_a3, p_w3, p_ff, b1 + L*DI, NQ, DI, 3*DM, 2);
        split_rowsA(p_ff, p_a3, NQ, 12);
        split_tr(W2 + (long)L*DI*DM, p_w3, DI, DM);
        gemm3(p_a3, p_w3, p_tmp, b2 + L*DM, NQ, DM, 3*DI, 1);
        add_ln_kernel<<<NQ, 256>>>(p_core, p_tmp, ln2g + L*DM, ln2b + L*DM);
    }

    // logits = core @ embW^T ; loss
    split_rowsA(p_core, p_a3, NQ, 10);
    gemm3(p_a3, p_emb3, p_logits, nullptr, NQ, NV, 3*DM, 0);
    loss_kernel<<<NQ, 256>>>(target, out);
}